// round 8
// baseline (speedup 1.0000x reference)
#include <cuda_runtime.h>
#include <cuda_bf16.h>
#include <cstdint>

#define R_TOTAL 32768   // 16384 b * 2 (values,mask)
#define NE      1024
#define H       128
#define NCH     32      // K-chunks of 32
#define NTILE   256     // 128-row M-tiles

// Scratch: vm[2b+0]=values row, vm[2b+1]=mask row.
__device__ float g_vm[(size_t)R_TOTAL * H];
// Per-tile completion flags (reset every launch).
__device__ int g_flag[NTILE];

// W pre-split into bf16 hi/lo, packed in m16n8k16 B-fragment order.
__device__ uint32_t g_Bh[64 * 16 * 32 * 2];
__device__ uint32_t g_Bl[64 * 16 * 32 * 2];

// ---------------------------------------------------------------------------
__global__ void zero_flags() { g_flag[threadIdx.x] = 0; }

// ---------------------------------------------------------------------------
// Kernel 0: split W -> bf16 hi/lo in B-fragment layout.
// ---------------------------------------------------------------------------
__global__ void prep_w(const float* __restrict__ W) {
    int idx = blockIdx.x * 256 + threadIdx.x;
    if (idx >= H * (NE / 2)) return;
    int h  = idx >> 9;
    int kp = idx & 511;
    int k  = kp * 2;

    float w0 = W[(size_t)h * NE + k];
    float w1 = W[(size_t)h * NE + k + 1];
    uint32_t b0 = __float_as_uint(w0), b1 = __float_as_uint(w1);
    uint32_t hi;
    asm("prmt.b32 %0, %1, %2, 0x7632;" : "=r"(hi) : "r"(b0), "r"(b1));
    float l0 = w0 - __uint_as_float(b0 & 0xFFFF0000u);
    float l1 = w1 - __uint_as_float(b1 & 0xFFFF0000u);
    uint32_t lo;
    asm("cvt.rn.bf16x2.f32 %0, %1, %2;" : "=r"(lo) : "f"(l1), "f"(l0));

    int kstep = kp >> 3;
    int natom = h >> 3;
    int lane  = 4 * (h & 7) + (kp & 3);
    int reg   = (kp >> 2) & 1;
    int out   = ((kstep * 16 + natom) * 32 + lane) * 2 + reg;
    g_Bh[out] = hi;
    g_Bl[out] = lo;
}

// ---------------------------------------------------------------------------
__device__ __forceinline__ void mma_bf16(float* d, const uint32_t* a,
                                         const uint32_t* b) {
    asm volatile(
        "mma.sync.aligned.m16n8k16.row.col.f32.bf16.bf16.f32 "
        "{%0,%1,%2,%3}, {%4,%5,%6,%7}, {%8,%9}, {%0,%1,%2,%3};"
        : "+f"(d[0]), "+f"(d[1]), "+f"(d[2]), "+f"(d[3])
        : "r"(a[0]), "r"(a[1]), "r"(a[2]), "r"(a[3]), "r"(b[0]), "r"(b[1]));
}
__device__ __forceinline__ uint32_t smem_u32(const void* p) {
    uint32_t a;
    asm("{ .reg .u64 t; cvta.to.shared.u64 t, %1; cvt.u32.u64 %0, t; }"
        : "=r"(a) : "l"(p));
    return a;
}
__device__ __forceinline__ void cp_async16(uint32_t s, const void* g) {
    asm volatile("cp.async.cg.shared.global [%0], [%1], 16;"
                 :: "r"(s), "l"(g) : "memory");
}
__device__ __forceinline__ float ex2f(float x) {
    float r;
    asm("ex2.approx.ftz.f32 %0, %1;" : "=f"(r) : "f"(x));
    return r;
}
// Reciprocal on the FMA pipe (no MUFU): bit-trick seed + 3 Newton steps.
__device__ __forceinline__ float nrcp(float s) {
    float y = __uint_as_float(0x7EF311C3u - __float_as_uint(s));
    y = y * fmaf(-s, y, 2.0f);
    y = y * fmaf(-s, y, 2.0f);
    y = y * fmaf(-s, y, 2.0f);
    return y;
}

// ---------------------------------------------------------------------------
// Fused kernel: even bid = gemm producer (tile t), odd bid = head consumer
// (same tile's 64 batches), synchronized via g_flag[t].
// ---------------------------------------------------------------------------
__global__ __launch_bounds__(256, 2) void fused(const float* __restrict__ X,
                                                const float* __restrict__ cov,
                                                const float* __restrict__ bias,
                                                float* __restrict__ out) {
    const int bid = blockIdx.x;
    const int t   = bid >> 1;
    const int tid  = threadIdx.x;
    const int wid  = tid >> 5;
    const int lane = tid & 31;

    if ((bid & 1) == 0) {
        // =================== PRODUCER: gemm tile t ===================
        __shared__ uint32_t sA[4096];       // 16KB: hi|lo
        __shared__ uint32_t sB[2][4096];    // 32KB
        uint32_t* sAh = sA;
        uint32_t* sAl = sA + 2048;

        const int row0 = t * 128;
        const int wm   = wid & 3;
        const int wn   = wid >> 2;
        const int ar[4] = { (tid + 0)   >> 3, (tid + 256) >> 3,
                            (tid + 512) >> 3, (tid + 768) >> 3 };
        const int ac4   = tid & 7;

        float acc[2][8][4];
        #pragma unroll
        for (int i = 0; i < 2; ++i)
            #pragma unroll
            for (int j = 0; j < 8; ++j)
                #pragma unroll
                for (int q = 0; q < 4; ++q) acc[i][j][q] = 0.f;

        float4 pref[4];
        #pragma unroll
        for (int j = 0; j < 4; ++j)
            pref[j] = __ldg(reinterpret_cast<const float4*>(
                                X + (size_t)(row0 + ar[j]) * NE) + ac4);
        {
            const char* gh = reinterpret_cast<const char*>(g_Bh);
            const char* gl = reinterpret_cast<const char*>(g_Bl);
            uint32_t db = smem_u32(sB[0]);
            int e = tid * 16;
            cp_async16(db + e,               gh + e);
            cp_async16(db + 8192 + e,        gl + e);
            cp_async16(db + e + 4096,        gh + e + 4096);
            cp_async16(db + 8192 + e + 4096, gl + e + 4096);
            asm volatile("cp.async.commit_group;" ::: "memory");
        }

        for (int c = 0; c < NCH; ++c) {
            const int cur = c & 1;
            __syncthreads();   // prior MMA reads of sA / sB[cur^1] retired

            #pragma unroll
            for (int j = 0; j < 4; ++j) {
                float4 v = pref[j];
                uint32_t x0 = __float_as_uint(v.x), x1 = __float_as_uint(v.y);
                uint32_t x2 = __float_as_uint(v.z), x3 = __float_as_uint(v.w);
                uint32_t hi01, hi23;
                asm("prmt.b32 %0, %1, %2, 0x7632;" : "=r"(hi01) : "r"(x0), "r"(x1));
                asm("prmt.b32 %0, %1, %2, 0x7632;" : "=r"(hi23) : "r"(x2), "r"(x3));
                float l0 = v.x - __uint_as_float(x0 & 0xFFFF0000u);
                float l1 = v.y - __uint_as_float(x1 & 0xFFFF0000u);
                float l2 = v.z - __uint_as_float(x2 & 0xFFFF0000u);
                float l3 = v.w - __uint_as_float(x3 & 0xFFFF0000u);
                uint32_t lo01, lo23;
                asm("cvt.rn.bf16x2.f32 %0, %1, %2;" : "=r"(lo01) : "f"(l1), "f"(l0));
                asm("cvt.rn.bf16x2.f32 %0, %1, %2;" : "=r"(lo23) : "f"(l3), "f"(l2));
                int rr = ar[j] & 15, a = ar[j] >> 4;
                #pragma unroll
                for (int p = 0; p < 2; ++p) {
                    int cc = 2 * ac4 + p;
                    int s  = cc >> 3;
                    int c8 = cc & 7;
                    int ln = (rr & 7) * 4 + (c8 & 3);
                    int rg = (rr >> 3) + 2 * (c8 >> 2);
                    int e  = ((s * 8 + a) * 32 + ln) * 4 + rg;
                    sAh[e] = p ? hi23 : hi01;
                    sAl[e] = p ? lo23 : lo01;
                }
            }

            if (c + 1 < NCH) {
                const char* gh = reinterpret_cast<const char*>(g_Bh + (c + 1) * 2048);
                const char* gl = reinterpret_cast<const char*>(g_Bl + (c + 1) * 2048);
                uint32_t db = smem_u32(sB[cur ^ 1]);
                int e = tid * 16;
                cp_async16(db + e,               gh + e);
                cp_async16(db + 8192 + e,        gl + e);
                cp_async16(db + e + 4096,        gh + e + 4096);
                cp_async16(db + 8192 + e + 4096, gl + e + 4096);
                asm volatile("cp.async.commit_group;" ::: "memory");
                const float* Xn = X + (c + 1) * 32;
                #pragma unroll
                for (int j = 0; j < 4; ++j)
                    pref[j] = __ldg(reinterpret_cast<const float4*>(
                                        Xn + (size_t)(row0 + ar[j]) * NE) + ac4);
                asm volatile("cp.async.wait_group 1;" ::: "memory");
            } else {
                asm volatile("cp.async.wait_group 0;" ::: "memory");
            }
            __syncthreads();   // sA converted + sB[cur] landed

            uint32_t* Bh = sB[cur];
            uint32_t* Bl = sB[cur] + 2048;

            #pragma unroll
            for (int s = 0; s < 2; ++s) {
                uint32_t ah[2][4], al[2][4];
                #pragma unroll
                for (int i = 0; i < 2; ++i) {
                    const uint32_t* pa = &sAh[((s * 8 + wm * 2 + i) * 32 + lane) * 4];
                    ah[i][0] = pa[0]; ah[i][1] = pa[1]; ah[i][2] = pa[2]; ah[i][3] = pa[3];
                    const uint32_t* pl = &sAl[((s * 8 + wm * 2 + i) * 32 + lane) * 4];
                    al[i][0] = pl[0]; al[i][1] = pl[1]; al[i][2] = pl[2]; al[i][3] = pl[3];
                }
                #pragma unroll
                for (int jh = 0; jh < 2; ++jh) {
                    uint32_t bh[4][2], bl[4][2];
                    #pragma unroll
                    for (int jj = 0; jj < 4; ++jj) {
                        int na = wn * 8 + jh * 4 + jj;
                        const uint32_t* pb = &Bh[(s * 16 + na) * 64 + lane * 2];
                        bh[jj][0] = pb[0]; bh[jj][1] = pb[1];
                        const uint32_t* ql = &Bl[(s * 16 + na) * 64 + lane * 2];
                        bl[jj][0] = ql[0]; bl[jj][1] = ql[1];
                    }
                    #pragma unroll
                    for (int i = 0; i < 2; ++i)
                        #pragma unroll
                        for (int jj = 0; jj < 4; ++jj) {
                            float* d = acc[i][jh * 4 + jj];
                            mma_bf16(d, ah[i], bh[jj]);
                            mma_bf16(d, ah[i], bl[jj]);
                            mma_bf16(d, al[i], bh[jj]);
                        }
                }
            }
        }

        // epilogue: fragments -> g_vm, then publish flag
        #pragma unroll
        for (int i = 0; i < 2; ++i) {
            int grow = row0 + wm * 32 + i * 16 + (lane >> 2);
            #pragma unroll
            for (int j = 0; j < 8; ++j) {
                int gcol = wn * 64 + j * 8 + 2 * (lane & 3);
                float2* p0 = reinterpret_cast<float2*>(&g_vm[(size_t)grow * H + gcol]);
                float2* p1 = reinterpret_cast<float2*>(&g_vm[(size_t)(grow + 8) * H + gcol]);
                *p0 = make_float2(acc[i][j][0], acc[i][j][1]);
                *p1 = make_float2(acc[i][j][2], acc[i][j][3]);
            }
        }
        __threadfence();
        __syncthreads();
        if (tid == 0) atomicExch(&g_flag[t], 1);

    } else {
        // =================== CONSUMER: head, batches [t*64, t*64+64) =========
        if (tid == 0) {
            while (atomicAdd(&g_flag[t], 0) == 0) __nanosleep(128);
        }
        __syncthreads();
        __threadfence();   // acquire: order vm reads after flag observation

        const float4 blf = __ldg(reinterpret_cast<const float4*>(bias) + lane);

        // warp handles 8 batches, as 4 pairs
        #pragma unroll 1
        for (int p = 0; p < 4; ++p) {
            const int b0 = t * 64 + wid * 8 + 2 * p;
            const int b1 = b0 + 1;

            // preload v/m rows (4 regs each): lane l holds h = l, l+32, l+64, l+96
            float v0[4], m0[4], v1[4], m1[4];
            #pragma unroll
            for (int r = 0; r < 4; ++r) {
                v0[r] = g_vm[(size_t)(2 * b0 + 0) * H + r * 32 + lane];
                m0[r] = g_vm[(size_t)(2 * b0 + 1) * H + r * 32 + lane]
                        * 1.4426950408889634f;
                v1[r] = g_vm[(size_t)(2 * b1 + 0) * H + r * 32 + lane];
                m1[r] = g_vm[(size_t)(2 * b1 + 1) * H + r * 32 + lane]
                        * 1.4426950408889634f;
            }

            float a00 = 0.f, a01 = 0.f, a02 = 0.f, a03 = 0.f;
            float a10 = 0.f, a11 = 0.f, a12 = 0.f, a13 = 0.f;

            #pragma unroll
            for (int hc = 0; hc < 4; ++hc) {
                #pragma unroll 8
                for (int i = 0; i < 32; ++i) {
                    const int h = hc * 32 + i;
                    const float mh0 = __shfl_sync(0xffffffffu, m0[hc], i);
                    const float mh1 = __shfl_sync(0xffffffffu, m1[hc], i);
                    const float4 c = __ldg(reinterpret_cast<const float4*>(
                                               cov + (size_t)h * H) + lane);
                    const float e00 = ex2f(mh0 * c.x), e01 = ex2f(mh0 * c.y);
                    const float e02 = ex2f(mh0 * c.z), e03 = ex2f(mh0 * c.w);
                    const float e10 = ex2f(mh1 * c.x), e11 = ex2f(mh1 * c.y);
                    const float e12 = ex2f(mh1 * c.z), e13 = ex2f(mh1 * c.w);
                    float s0 = (e00 + e01) + (e02 + e03);
                    float s1 = (e10 + e11) + (e12 + e13);
                    #pragma unroll
                    for (int d = 16; d > 0; d >>= 1) {
                        s0 += __shfl_xor_sync(0xffffffffu, s0, d);
                        s1 += __shfl_xor_sync(0xffffffffu, s1, d);
                    }
                    const float vh0 = __shfl_sync(0xffffffffu, v0[hc], i);
                    const float vh1 = __shfl_sync(0xffffffffu, v1[hc], i);
                    const float w0 = vh0 * nrcp(s0);
                    const float w1 = vh1 * nrcp(s1);
                    a00 = fmaf(w0, e00, a00); a01 = fmaf(w0, e01, a01);
                    a02 = fmaf(w0, e02, a02); a03 = fmaf(w0, e03, a03);
                    a10 = fmaf(w1, e10, a10); a11 = fmaf(w1, e11, a11);
                    a12 = fmaf(w1, e12, a12); a13 = fmaf(w1, e13, a13);
                }
            }

            *reinterpret_cast<float4*>(&out[(size_t)b0 * H + 4 * lane]) =
                make_float4(a00 + blf.x, a01 + blf.y, a02 + blf.z, a03 + blf.w);
            *reinterpret_cast<float4*>(&out[(size_t)b1 * H + 4 * lane]) =
                make_float4(a10 + blf.x, a11 + blf.y, a12 + blf.z, a13 + blf.w);
        }
    }
}

// ---------------------------------------------------------------------------
extern "C" void kernel_launch(void* const* d_in, const int* in_sizes, int n_in,
                              void* d_out, int out_size) {
    const float* x    = (const float*)d_in[0];  // [16384,2,1024]
    const float* W    = (const float*)d_in[1];  // [128,1024]
    const float* cov  = (const float*)d_in[2];  // [128,128]
    const float* bias = (const float*)d_in[3];  // [128]
    float*       out  = (float*)d_out;          // [16384,128]

    zero_flags<<<1, NTILE>>>();
    prep_w<<<(H * NE / 2 + 255) / 256, 256>>>(W);
    fused<<<2 * NTILE, 256>>>(x, cov, bias, out);
}

// round 9
// speedup vs baseline: 1.4327x; 1.4327x over previous
#include <cuda_runtime.h>
#include <cuda_bf16.h>
#include <cstdint>

#define R_TOTAL 32768   // 16384 b * 2 (values,mask)
#define NE      1024
#define H       128
#define NCH     32      // K-chunks of 32

// Scratch: vm[2b+0]=values row, vm[2b+1]=mask row.
__device__ float g_vm[(size_t)R_TOTAL * H];

// W pre-split into bf16 hi/lo, packed in m16n8k16 B-fragment order.
__device__ uint32_t g_Bh[64 * 16 * 32 * 2];
__device__ uint32_t g_Bl[64 * 16 * 32 * 2];

// ---------------------------------------------------------------------------
// Kernel 0: split W -> bf16 hi/lo in B-fragment layout.
// ---------------------------------------------------------------------------
__global__ void prep_w(const float* __restrict__ W) {
    int idx = blockIdx.x * 256 + threadIdx.x;
    if (idx >= H * (NE / 2)) return;
    int h  = idx >> 9;
    int kp = idx & 511;
    int k  = kp * 2;

    float w0 = W[(size_t)h * NE + k];
    float w1 = W[(size_t)h * NE + k + 1];
    uint32_t b0 = __float_as_uint(w0), b1 = __float_as_uint(w1);
    uint32_t hi;
    asm("prmt.b32 %0, %1, %2, 0x7632;" : "=r"(hi) : "r"(b0), "r"(b1));
    float l0 = w0 - __uint_as_float(b0 & 0xFFFF0000u);
    float l1 = w1 - __uint_as_float(b1 & 0xFFFF0000u);
    uint32_t lo;
    asm("cvt.rn.bf16x2.f32 %0, %1, %2;" : "=r"(lo) : "f"(l1), "f"(l0));

    int kstep = kp >> 3;
    int natom = h >> 3;
    int lane  = 4 * (h & 7) + (kp & 3);
    int reg   = (kp >> 2) & 1;
    int out   = ((kstep * 16 + natom) * 32 + lane) * 2 + reg;
    g_Bh[out] = hi;
    g_Bl[out] = lo;
}

// ---------------------------------------------------------------------------
__device__ __forceinline__ void mma_bf16(float* d, const uint32_t* a,
                                         const uint32_t* b) {
    asm volatile(
        "mma.sync.aligned.m16n8k16.row.col.f32.bf16.bf16.f32 "
        "{%0,%1,%2,%3}, {%4,%5,%6,%7}, {%8,%9}, {%0,%1,%2,%3};"
        : "+f"(d[0]), "+f"(d[1]), "+f"(d[2]), "+f"(d[3])
        : "r"(a[0]), "r"(a[1]), "r"(a[2]), "r"(a[3]), "r"(b[0]), "r"(b[1]));
}
__device__ __forceinline__ uint32_t smem_u32(const void* p) {
    uint32_t a;
    asm("{ .reg .u64 t; cvta.to.shared.u64 t, %1; cvt.u32.u64 %0, t; }"
        : "=r"(a) : "l"(p));
    return a;
}
__device__ __forceinline__ void cp_async16(uint32_t s, const void* g) {
    asm volatile("cp.async.cg.shared.global [%0], [%1], 16;"
                 :: "r"(s), "l"(g) : "memory");
}
__device__ __forceinline__ float ex2f(float x) {
    float r;
    asm("ex2.approx.ftz.f32 %0, %1;" : "=f"(r) : "f"(x));
    return r;
}
// Reciprocal on the FMA pipe (no MUFU): bit-trick seed + 3 Newton steps.
__device__ __forceinline__ float nrcp(float s) {
    float y = __uint_as_float(0x7EF311C3u - __float_as_uint(s));
    y = y * fmaf(-s, y, 2.0f);
    y = y * fmaf(-s, y, 2.0f);
    y = y * fmaf(-s, y, 2.0f);
    return y;
}

// ---------------------------------------------------------------------------
// Kernel 1: vm = X @ W^T via mma.sync bf16 3-term split (R7, unchanged).
// ---------------------------------------------------------------------------
__global__ __launch_bounds__(256, 2) void gemm_vm_tc(const float* __restrict__ X) {
    __shared__ uint32_t sA[4096];       // 16KB: hi[2048] | lo[2048]
    __shared__ uint32_t sB[2][4096];    // 32KB
    uint32_t* sAh = sA;
    uint32_t* sAl = sA + 2048;

    const int tid  = threadIdx.x;
    const int wid  = tid >> 5;
    const int lane = tid & 31;
    const int row0 = blockIdx.x * 128;
    const int wm   = wid & 3;
    const int wn   = wid >> 2;

    const int ar[4] = { (tid + 0)   >> 3, (tid + 256) >> 3,
                        (tid + 512) >> 3, (tid + 768) >> 3 };
    const int ac4   = tid & 7;

    float acc[2][8][4];
    #pragma unroll
    for (int i = 0; i < 2; ++i)
        #pragma unroll
        for (int j = 0; j < 8; ++j)
            #pragma unroll
            for (int q = 0; q < 4; ++q) acc[i][j][q] = 0.f;

    float4 pref[4];
    #pragma unroll
    for (int j = 0; j < 4; ++j)
        pref[j] = __ldg(reinterpret_cast<const float4*>(
                            X + (size_t)(row0 + ar[j]) * NE) + ac4);
    {
        const char* gh = reinterpret_cast<const char*>(g_Bh);
        const char* gl = reinterpret_cast<const char*>(g_Bl);
        uint32_t db = smem_u32(sB[0]);
        int e = tid * 16;
        cp_async16(db + e,               gh + e);
        cp_async16(db + 8192 + e,        gl + e);
        cp_async16(db + e + 4096,        gh + e + 4096);
        cp_async16(db + 8192 + e + 4096, gl + e + 4096);
        asm volatile("cp.async.commit_group;" ::: "memory");
    }

    for (int c = 0; c < NCH; ++c) {
        const int cur = c & 1;
        __syncthreads();   // prior MMA reads of sA / sB[cur^1] retired

        #pragma unroll
        for (int j = 0; j < 4; ++j) {
            float4 v = pref[j];
            uint32_t x0 = __float_as_uint(v.x), x1 = __float_as_uint(v.y);
            uint32_t x2 = __float_as_uint(v.z), x3 = __float_as_uint(v.w);
            uint32_t hi01, hi23;
            asm("prmt.b32 %0, %1, %2, 0x7632;" : "=r"(hi01) : "r"(x0), "r"(x1));
            asm("prmt.b32 %0, %1, %2, 0x7632;" : "=r"(hi23) : "r"(x2), "r"(x3));
            float l0 = v.x - __uint_as_float(x0 & 0xFFFF0000u);
            float l1 = v.y - __uint_as_float(x1 & 0xFFFF0000u);
            float l2 = v.z - __uint_as_float(x2 & 0xFFFF0000u);
            float l3 = v.w - __uint_as_float(x3 & 0xFFFF0000u);
            uint32_t lo01, lo23;
            asm("cvt.rn.bf16x2.f32 %0, %1, %2;" : "=r"(lo01) : "f"(l1), "f"(l0));
            asm("cvt.rn.bf16x2.f32 %0, %1, %2;" : "=r"(lo23) : "f"(l3), "f"(l2));
            int rr = ar[j] & 15, a = ar[j] >> 4;
            #pragma unroll
            for (int p = 0; p < 2; ++p) {
                int cc = 2 * ac4 + p;
                int s  = cc >> 3;
                int c8 = cc & 7;
                int ln = (rr & 7) * 4 + (c8 & 3);
                int rg = (rr >> 3) + 2 * (c8 >> 2);
                int e  = ((s * 8 + a) * 32 + ln) * 4 + rg;
                sAh[e] = p ? hi23 : hi01;
                sAl[e] = p ? lo23 : lo01;
            }
        }

        if (c + 1 < NCH) {
            const char* gh = reinterpret_cast<const char*>(g_Bh + (c + 1) * 2048);
            const char* gl = reinterpret_cast<const char*>(g_Bl + (c + 1) * 2048);
            uint32_t db = smem_u32(sB[cur ^ 1]);
            int e = tid * 16;
            cp_async16(db + e,               gh + e);
            cp_async16(db + 8192 + e,        gl + e);
            cp_async16(db + e + 4096,        gh + e + 4096);
            cp_async16(db + 8192 + e + 4096, gl + e + 4096);
            asm volatile("cp.async.commit_group;" ::: "memory");
            const float* Xn = X + (c + 1) * 32;
            #pragma unroll
            for (int j = 0; j < 4; ++j)
                pref[j] = __ldg(reinterpret_cast<const float4*>(
                                    Xn + (size_t)(row0 + ar[j]) * NE) + ac4);
            asm volatile("cp.async.wait_group 1;" ::: "memory");
        } else {
            asm volatile("cp.async.wait_group 0;" ::: "memory");
        }
        __syncthreads();   // sA converted + sB[cur] landed

        uint32_t* Bh = sB[cur];
        uint32_t* Bl = sB[cur] + 2048;

        #pragma unroll
        for (int s = 0; s < 2; ++s) {
            uint32_t ah[2][4], al[2][4];
            #pragma unroll
            for (int i = 0; i < 2; ++i) {
                const uint32_t* pa = &sAh[((s * 8 + wm * 2 + i) * 32 + lane) * 4];
                ah[i][0] = pa[0]; ah[i][1] = pa[1]; ah[i][2] = pa[2]; ah[i][3] = pa[3];
                const uint32_t* pl = &sAl[((s * 8 + wm * 2 + i) * 32 + lane) * 4];
                al[i][0] = pl[0]; al[i][1] = pl[1]; al[i][2] = pl[2]; al[i][3] = pl[3];
            }
            #pragma unroll
            for (int jh = 0; jh < 2; ++jh) {
                uint32_t bh[4][2], bl[4][2];
                #pragma unroll
                for (int jj = 0; jj < 4; ++jj) {
                    int na = wn * 8 + jh * 4 + jj;
                    const uint32_t* pb = &Bh[(s * 16 + na) * 64 + lane * 2];
                    bh[jj][0] = pb[0]; bh[jj][1] = pb[1];
                    const uint32_t* ql = &Bl[(s * 16 + na) * 64 + lane * 2];
                    bl[jj][0] = ql[0]; bl[jj][1] = ql[1];
                }
                #pragma unroll
                for (int i = 0; i < 2; ++i)
                    #pragma unroll
                    for (int jj = 0; jj < 4; ++jj) {
                        float* d = acc[i][jh * 4 + jj];
                        mma_bf16(d, ah[i], bh[jj]);
                        mma_bf16(d, ah[i], bl[jj]);
                        mma_bf16(d, al[i], bh[jj]);
                    }
            }
        }
    }

    #pragma unroll
    for (int i = 0; i < 2; ++i) {
        int grow = row0 + wm * 32 + i * 16 + (lane >> 2);
        #pragma unroll
        for (int j = 0; j < 8; ++j) {
            int gcol = wn * 64 + j * 8 + 2 * (lane & 3);
            float2* p0 = reinterpret_cast<float2*>(&g_vm[(size_t)grow * H + gcol]);
            float2* p1 = reinterpret_cast<float2*>(&g_vm[(size_t)(grow + 8) * H + gcol]);
            *p0 = make_float2(acc[i][j][0], acc[i][j][1]);
            *p1 = make_float2(acc[i][j][2], acc[i][j][3]);
        }
    }
}

// ---------------------------------------------------------------------------
// Kernel 2: fused softmax head, batch-PAIR processing (one cov load feeds 2
// batches), Newton rcp on FMA pipe. Grid 512 x 256; warp = 4 batches (2 pairs).
// ---------------------------------------------------------------------------
__global__ __launch_bounds__(256) void head_out(const float* __restrict__ cov,
                                                const float* __restrict__ bias,
                                                float* __restrict__ out) {
    const int tid  = threadIdx.x;
    const int wid  = tid >> 5;
    const int lane = tid & 31;
    const int gw   = blockIdx.x * 8 + wid;   // global warp id, 0..4095

    const float4 blf = __ldg(reinterpret_cast<const float4*>(bias) + lane);

    #pragma unroll 1
    for (int p = 0; p < 2; ++p) {
        const int b0 = gw * 4 + 2 * p;
        const int b1 = b0 + 1;

        // preload v/m rows (4 regs each): lane l holds h = l, l+32, l+64, l+96
        float v0[4], m0[4], v1[4], m1[4];
        #pragma unroll
        for (int r = 0; r < 4; ++r) {
            v0[r] = g_vm[(size_t)(2 * b0 + 0) * H + r * 32 + lane];
            m0[r] = g_vm[(size_t)(2 * b0 + 1) * H + r * 32 + lane]
                    * 1.4426950408889634f;
            v1[r] = g_vm[(size_t)(2 * b1 + 0) * H + r * 32 + lane];
            m1[r] = g_vm[(size_t)(2 * b1 + 1) * H + r * 32 + lane]
                    * 1.4426950408889634f;
        }

        float a00 = 0.f, a01 = 0.f, a02 = 0.f, a03 = 0.f;
        float a10 = 0.f, a11 = 0.f, a12 = 0.f, a13 = 0.f;

        #pragma unroll
        for (int hc = 0; hc < 4; ++hc) {
            #pragma unroll 8
            for (int i = 0; i < 32; ++i) {
                const int h = hc * 32 + i;
                const float mh0 = __shfl_sync(0xffffffffu, m0[hc], i);
                const float mh1 = __shfl_sync(0xffffffffu, m1[hc], i);
                const float4 c = __ldg(reinterpret_cast<const float4*>(
                                           cov + (size_t)h * H) + lane);
                const float e00 = ex2f(mh0 * c.x), e01 = ex2f(mh0 * c.y);
                const float e02 = ex2f(mh0 * c.z), e03 = ex2f(mh0 * c.w);
                const float e10 = ex2f(mh1 * c.x), e11 = ex2f(mh1 * c.y);
                const float e12 = ex2f(mh1 * c.z), e13 = ex2f(mh1 * c.w);
                float s0 = (e00 + e01) + (e02 + e03);
                float s1 = (e10 + e11) + (e12 + e13);
                #pragma unroll
                for (int d = 16; d > 0; d >>= 1) {
                    s0 += __shfl_xor_sync(0xffffffffu, s0, d);
                    s1 += __shfl_xor_sync(0xffffffffu, s1, d);
                }
                const float vh0 = __shfl_sync(0xffffffffu, v0[hc], i);
                const float vh1 = __shfl_sync(0xffffffffu, v1[hc], i);
                const float w0 = vh0 * nrcp(s0);
                const float w1 = vh1 * nrcp(s1);
                a00 = fmaf(w0, e00, a00); a01 = fmaf(w0, e01, a01);
                a02 = fmaf(w0, e02, a02); a03 = fmaf(w0, e03, a03);
                a10 = fmaf(w1, e10, a10); a11 = fmaf(w1, e11, a11);
                a12 = fmaf(w1, e12, a12); a13 = fmaf(w1, e13, a13);
            }
        }

        *reinterpret_cast<float4*>(&out[(size_t)b0 * H + 4 * lane]) =
            make_float4(a00 + blf.x, a01 + blf.y, a02 + blf.z, a03 + blf.w);
        *reinterpret_cast<float4*>(&out[(size_t)b1 * H + 4 * lane]) =
            make_float4(a10 + blf.x, a11 + blf.y, a12 + blf.z, a13 + blf.w);
    }
}

// ---------------------------------------------------------------------------
extern "C" void kernel_launch(void* const* d_in, const int* in_sizes, int n_in,
                              void* d_out, int out_size) {
    const float* x    = (const float*)d_in[0];  // [16384,2,1024]
    const float* W    = (const float*)d_in[1];  // [128,1024]
    const float* cov  = (const float*)d_in[2];  // [128,128]
    const float* bias = (const float*)d_in[3];  // [128]
    float*       out  = (float*)d_out;          // [16384,128]

    prep_w<<<(H * NE / 2 + 255) / 256, 256>>>(W);
    gemm_vm_tc<<<R_TOTAL / 128, 256>>>(x);
    head_out<<<512, 256>>>(cov, bias, out);
}

// round 11
// speedup vs baseline: 1.6278x; 1.1362x over previous
#include <cuda_runtime.h>
#include <cuda_bf16.h>
#include <cstdint>

#define R_TOTAL 32768   // 16384 b * 2 (values,mask)
#define NE      1024
#define H       128
#define NCH     32      // K-chunks of 32

// Scratch: vm[2b+0]=values row, vm[2b+1]=mask row.
__device__ float g_vm[(size_t)R_TOTAL * H];

// W pre-split into bf16 hi/lo, packed in PAIRED m16n8k16 B-fragment order:
//   [kstep(64)][pair(8)][lane(32)][q(2)*2+reg]  (natom = 2*pair + q)
__device__ uint32_t g_Bh[64 * 8 * 32 * 4];
__device__ uint32_t g_Bl[64 * 8 * 32 * 4];

// ---------------------------------------------------------------------------
// Kernel 0: split W -> bf16 hi/lo in paired B-fragment layout.
// ---------------------------------------------------------------------------
__global__ void prep_w(const float* __restrict__ W) {
    int idx = blockIdx.x * 256 + threadIdx.x;
    if (idx >= H * (NE / 2)) return;
    int h  = idx >> 9;
    int kp = idx & 511;
    int k  = kp * 2;

    float w0 = W[(size_t)h * NE + k];
    float w1 = W[(size_t)h * NE + k + 1];
    uint32_t b0 = __float_as_uint(w0), b1 = __float_as_uint(w1);
    uint32_t hi;
    asm("prmt.b32 %0, %1, %2, 0x7632;" : "=r"(hi) : "r"(b0), "r"(b1));
    float l0 = w0 - __uint_as_float(b0 & 0xFFFF0000u);
    float l1 = w1 - __uint_as_float(b1 & 0xFFFF0000u);
    uint32_t lo;
    asm("cvt.rn.bf16x2.f32 %0, %1, %2;" : "=r"(lo) : "f"(l1), "f"(l0));

    int kstep = kp >> 3;
    int natom = h >> 3;
    int pair  = natom >> 1;
    int q     = natom & 1;
    int lane  = 4 * (h & 7) + (kp & 3);
    int reg   = (kp >> 2) & 1;
    int out   = ((kstep * 8 + pair) * 32 + lane) * 4 + q * 2 + reg;
    g_Bh[out] = hi;
    g_Bl[out] = lo;
}

// ---------------------------------------------------------------------------
__device__ __forceinline__ void mma_bf16(float* d, const uint32_t* a,
                                         uint32_t b0, uint32_t b1) {
    asm volatile(
        "mma.sync.aligned.m16n8k16.row.col.f32.bf16.bf16.f32 "
        "{%0,%1,%2,%3}, {%4,%5,%6,%7}, {%8,%9}, {%0,%1,%2,%3};"
        : "+f"(d[0]), "+f"(d[1]), "+f"(d[2]), "+f"(d[3])
        : "r"(a[0]), "r"(a[1]), "r"(a[2]), "r"(a[3]), "r"(b0), "r"(b1));
}
__device__ __forceinline__ uint32_t smem_u32(const void* p) {
    uint32_t a;
    asm("{ .reg .u64 t; cvta.to.shared.u64 t, %1; cvt.u32.u64 %0, t; }"
        : "=r"(a) : "l"(p));
    return a;
}
__device__ __forceinline__ void cp_async16(uint32_t s, const void* g) {
    asm volatile("cp.async.cg.shared.global [%0], [%1], 16;"
                 :: "r"(s), "l"(g) : "memory");
}
__device__ __forceinline__ float ex2f(float x) {
    float r;
    asm("ex2.approx.ftz.f32 %0, %1;" : "=f"(r) : "f"(x));
    return r;
}
// Reciprocal on the FMA pipe (no MUFU): bit-trick seed + 3 Newton steps.
__device__ __forceinline__ float nrcp(float s) {
    float y = __uint_as_float(0x7EF311C3u - __float_as_uint(s));
    y = y * fmaf(-s, y, 2.0f);
    y = y * fmaf(-s, y, 2.0f);
    y = y * fmaf(-s, y, 2.0f);
    return y;
}

// ---------------------------------------------------------------------------
// Kernel 1: vm = X @ W^T via mma.sync bf16 3-term split; B loads via LDS.128.
// ---------------------------------------------------------------------------
__global__ __launch_bounds__(256, 2) void gemm_vm_tc(const float* __restrict__ X) {
    __shared__ uint32_t sA[4096];       // 16KB: hi[2048] | lo[2048]
    __shared__ uint32_t sB[2][4096];    // 32KB
    uint32_t* sAh = sA;
    uint32_t* sAl = sA + 2048;

    const int tid  = threadIdx.x;
    const int wid  = tid >> 5;
    const int lane = tid & 31;
    const int row0 = blockIdx.x * 128;
    const int wm   = wid & 3;
    const int wn   = wid >> 2;

    const int ar[4] = { (tid + 0)   >> 3, (tid + 256) >> 3,
                        (tid + 512) >> 3, (tid + 768) >> 3 };
    const int ac4   = tid & 7;

    float acc[2][8][4];
    #pragma unroll
    for (int i = 0; i < 2; ++i)
        #pragma unroll
        for (int j = 0; j < 8; ++j)
            #pragma unroll
            for (int q = 0; q < 4; ++q) acc[i][j][q] = 0.f;

    float4 pref[4];
    #pragma unroll
    for (int j = 0; j < 4; ++j)
        pref[j] = __ldg(reinterpret_cast<const float4*>(
                            X + (size_t)(row0 + ar[j]) * NE) + ac4);
    {
        const char* gh = reinterpret_cast<const char*>(g_Bh);
        const char* gl = reinterpret_cast<const char*>(g_Bl);
        uint32_t db = smem_u32(sB[0]);
        int e = tid * 16;
        cp_async16(db + e,               gh + e);
        cp_async16(db + 8192 + e,        gl + e);
        cp_async16(db + e + 4096,        gh + e + 4096);
        cp_async16(db + 8192 + e + 4096, gl + e + 4096);
        asm volatile("cp.async.commit_group;" ::: "memory");
    }

    for (int c = 0; c < NCH; ++c) {
        const int cur = c & 1;
        __syncthreads();   // prior MMA reads of sA / sB[cur^1] retired

        #pragma unroll
        for (int j = 0; j < 4; ++j) {
            float4 v = pref[j];
            uint32_t x0 = __float_as_uint(v.x), x1 = __float_as_uint(v.y);
            uint32_t x2 = __float_as_uint(v.z), x3 = __float_as_uint(v.w);
            uint32_t hi01, hi23;
            asm("prmt.b32 %0, %1, %2, 0x7632;" : "=r"(hi01) : "r"(x0), "r"(x1));
            asm("prmt.b32 %0, %1, %2, 0x7632;" : "=r"(hi23) : "r"(x2), "r"(x3));
            float l0 = v.x - __uint_as_float(x0 & 0xFFFF0000u);
            float l1 = v.y - __uint_as_float(x1 & 0xFFFF0000u);
            float l2 = v.z - __uint_as_float(x2 & 0xFFFF0000u);
            float l3 = v.w - __uint_as_float(x3 & 0xFFFF0000u);
            uint32_t lo01, lo23;
            asm("cvt.rn.bf16x2.f32 %0, %1, %2;" : "=r"(lo01) : "f"(l1), "f"(l0));
            asm("cvt.rn.bf16x2.f32 %0, %1, %2;" : "=r"(lo23) : "f"(l3), "f"(l2));
            int rr = ar[j] & 15, a = ar[j] >> 4;
            #pragma unroll
            for (int p = 0; p < 2; ++p) {
                int cc = 2 * ac4 + p;
                int s  = cc >> 3;
                int c8 = cc & 7;
                int ln = (rr & 7) * 4 + (c8 & 3);
                int rg = (rr >> 3) + 2 * (c8 >> 2);
                int e  = ((s * 8 + a) * 32 + ln) * 4 + rg;
                sAh[e] = p ? hi23 : hi01;
                sAl[e] = p ? lo23 : lo01;
            }
        }

        if (c + 1 < NCH) {
            const char* gh = reinterpret_cast<const char*>(g_Bh + (c + 1) * 2048);
            const char* gl = reinterpret_cast<const char*>(g_Bl + (c + 1) * 2048);
            uint32_t db = smem_u32(sB[cur ^ 1]);
            int e = tid * 16;
            cp_async16(db + e,               gh + e);
            cp_async16(db + 8192 + e,        gl + e);
            cp_async16(db + e + 4096,        gh + e + 4096);
            cp_async16(db + 8192 + e + 4096, gl + e + 4096);
            asm volatile("cp.async.commit_group;" ::: "memory");
            const float* Xn = X + (c + 1) * 32;
            #pragma unroll
            for (int j = 0; j < 4; ++j)
                pref[j] = __ldg(reinterpret_cast<const float4*>(
                                    Xn + (size_t)(row0 + ar[j]) * NE) + ac4);
            asm volatile("cp.async.wait_group 1;" ::: "memory");
        } else {
            asm volatile("cp.async.wait_group 0;" ::: "memory");
        }
        __syncthreads();   // sA converted + sB[cur] landed

        uint32_t* Bh = sB[cur];
        uint32_t* Bl = sB[cur] + 2048;

        #pragma unroll
        for (int s = 0; s < 2; ++s) {
            uint32_t ah[2][4], al[2][4];
            #pragma unroll
            for (int i = 0; i < 2; ++i) {
                const uint32_t* pa = &sAh[((s * 8 + wm * 2 + i) * 32 + lane) * 4];
                ah[i][0] = pa[0]; ah[i][1] = pa[1]; ah[i][2] = pa[2]; ah[i][3] = pa[3];
                const uint32_t* pl = &sAl[((s * 8 + wm * 2 + i) * 32 + lane) * 4];
                al[i][0] = pl[0]; al[i][1] = pl[1]; al[i][2] = pl[2]; al[i][3] = pl[3];
            }
            #pragma unroll
            for (int jh = 0; jh < 2; ++jh) {
                uint4 bhp[2], blp[2];
                #pragma unroll
                for (int jp = 0; jp < 2; ++jp) {
                    int pi = wn * 4 + jh * 2 + jp;
                    bhp[jp] = *reinterpret_cast<const uint4*>(
                        &Bh[((s * 8 + pi) * 32 + lane) * 4]);
                    blp[jp] = *reinterpret_cast<const uint4*>(
                        &Bl[((s * 8 + pi) * 32 + lane) * 4]);
                }
                const uint32_t bh[4][2] = {
                    {bhp[0].x, bhp[0].y}, {bhp[0].z, bhp[0].w},
                    {bhp[1].x, bhp[1].y}, {bhp[1].z, bhp[1].w}};
                const uint32_t bl[4][2] = {
                    {blp[0].x, blp[0].y}, {blp[0].z, blp[0].w},
                    {blp[1].x, blp[1].y}, {blp[1].z, blp[1].w}};
                #pragma unroll
                for (int i = 0; i < 2; ++i)
                    #pragma unroll
                    for (int jj = 0; jj < 4; ++jj) {
                        float* d = acc[i][jh * 4 + jj];
                        mma_bf16(d, ah[i], bh[jj][0], bh[jj][1]);
                        mma_bf16(d, ah[i], bl[jj][0], bl[jj][1]);
                        mma_bf16(d, al[i], bh[jj][0], bh[jj][1]);
                    }
            }
        }
    }

    #pragma unroll
    for (int i = 0; i < 2; ++i) {
        int grow = row0 + wm * 32 + i * 16 + (lane >> 2);
        #pragma unroll
        for (int j = 0; j < 8; ++j) {
            int gcol = wn * 64 + j * 8 + 2 * (lane & 3);
            float2* p0 = reinterpret_cast<float2*>(&g_vm[(size_t)grow * H + gcol]);
            float2* p1 = reinterpret_cast<float2*>(&g_vm[(size_t)(grow + 8) * H + gcol]);
            *p0 = make_float2(acc[i][j][0], acc[i][j][1]);
            *p1 = make_float2(acc[i][j][2], acc[i][j][3]);
        }
    }
}

// ---------------------------------------------------------------------------
// Kernel 2: fused softmax head. R2 CTA structure (128 thr, warp = 32 h,
// smem combine) but TWO batches per CTA: one cov LDG + one packed LDS.64
// (m-pair / v-pair) feed both batches. Grid 8192.
// ---------------------------------------------------------------------------
__global__ __launch_bounds__(128) void head_out(const float* __restrict__ cov,
                                                const float* __restrict__ bias,
                                                float* __restrict__ out) {
    __shared__ float2 mv[H];           // (m0*log2e, m1*log2e)
    __shared__ float2 vv[H];           // (v0, v1)
    __shared__ float  part[4][2][H];   // 4KB partials

    const int b0 = blockIdx.x * 2;
    const int b1 = b0 + 1;
    const int t  = threadIdx.x;
    const int w  = t >> 5;
    const int l  = t & 31;
    const int hbase = w * 32;

    mv[t] = make_float2(g_vm[(size_t)(2 * b0 + 1) * H + t] * 1.4426950408889634f,
                        g_vm[(size_t)(2 * b1 + 1) * H + t] * 1.4426950408889634f);
    vv[t] = make_float2(g_vm[(size_t)(2 * b0 + 0) * H + t],
                        g_vm[(size_t)(2 * b1 + 0) * H + t]);
    __syncthreads();

    float a00 = 0.f, a01 = 0.f, a02 = 0.f, a03 = 0.f;
    float a10 = 0.f, a11 = 0.f, a12 = 0.f, a13 = 0.f;

    #pragma unroll 8
    for (int i = 0; i < 32; ++i) {
        const int h = hbase + i;
        const float2 m = mv[h];
        const float4 c = __ldg(reinterpret_cast<const float4*>(
                                   cov + (size_t)h * H) + l);
        const float e00 = ex2f(m.x * c.x), e01 = ex2f(m.x * c.y);
        const float e02 = ex2f(m.x * c.z), e03 = ex2f(m.x * c.w);
        const float e10 = ex2f(m.y * c.x), e11 = ex2f(m.y * c.y);
        const float e12 = ex2f(m.y * c.z), e13 = ex2f(m.y * c.w);
        float s0 = (e00 + e01) + (e02 + e03);
        float s1 = (e10 + e11) + (e12 + e13);
        #pragma unroll
        for (int d = 16; d > 0; d >>= 1) {
            s0 += __shfl_xor_sync(0xffffffffu, s0, d);
            s1 += __shfl_xor_sync(0xffffffffu, s1, d);
        }
        const float2 v = vv[h];
        const float w0 = v.x * nrcp(s0);
        const float w1 = v.y * nrcp(s1);
        a00 = fmaf(w0, e00, a00); a01 = fmaf(w0, e01, a01);
        a02 = fmaf(w0, e02, a02); a03 = fmaf(w0, e03, a03);
        a10 = fmaf(w1, e10, a10); a11 = fmaf(w1, e11, a11);
        a12 = fmaf(w1, e12, a12); a13 = fmaf(w1, e13, a13);
    }

    *reinterpret_cast<float4*>(&part[w][0][4 * l]) = make_float4(a00, a01, a02, a03);
    *reinterpret_cast<float4*>(&part[w][1][4 * l]) = make_float4(a10, a11, a12, a13);
    __syncthreads();

    const float bb = __ldg(bias + t);
    out[(size_t)b0 * H + t] = ((part[0][0][t] + part[1][0][t]) +
                               (part[2][0][t] + part[3][0][t])) + bb;
    out[(size_t)b1 * H + t] = ((part[0][1][t] + part[1][1][t]) +
                               (part[2][1][t] + part[3][1][t])) + bb;
}

// ---------------------------------------------------------------------------
extern "C" void kernel_launch(void* const* d_in, const int* in_sizes, int n_in,
                              void* d_out, int out_size) {
    const float* x    = (const float*)d_in[0];  // [16384,2,1024]
    const float* W    = (const float*)d_in[1];  // [128,1024]
    const float* cov  = (const float*)d_in[2];  // [128,128]
    const float* bias = (const float*)d_in[3];  // [128]
    float*       out  = (float*)d_out;          // [16384,128]

    prep_w<<<(H * NE / 2 + 255) / 256, 256>>>(W);
    gemm_vm_tc<<<R_TOTAL / 128, 256>>>(x);
    head_out<<<8192, 128>>>(cov, bias, out);
}

// round 13
// speedup vs baseline: 1.6330x; 1.0032x over previous
#include <cuda_runtime.h>
#include <cuda_bf16.h>
#include <cstdint>

#define R_TOTAL 32768   // 16384 b * 2 (values,mask)
#define NE      1024
#define H       128
#define NCH     32      // K-chunks of 32

// Scratch: vm[2b+0]=values row, vm[2b+1]=mask row.
__device__ float g_vm[(size_t)R_TOTAL * H];

// W pre-split into bf16 hi/lo, packed in PAIRED m16n8k16 B-fragment order:
//   [kstep(64)][pair(8)][lane(32)][q(2)*2+reg]  (natom = 2*pair + q)
__device__ uint32_t g_Bh[64 * 8 * 32 * 4];
__device__ uint32_t g_Bl[64 * 8 * 32 * 4];

// ---------------------------------------------------------------------------
// Kernel 0: split W -> bf16 hi/lo in paired B-fragment layout.
// ---------------------------------------------------------------------------
__global__ void prep_w(const float* __restrict__ W) {
    int idx = blockIdx.x * 256 + threadIdx.x;
    if (idx >= H * (NE / 2)) return;
    int h  = idx >> 9;
    int kp = idx & 511;
    int k  = kp * 2;

    float w0 = W[(size_t)h * NE + k];
    float w1 = W[(size_t)h * NE + k + 1];
    uint32_t b0 = __float_as_uint(w0), b1 = __float_as_uint(w1);
    uint32_t hi;
    asm("prmt.b32 %0, %1, %2, 0x7632;" : "=r"(hi) : "r"(b0), "r"(b1));
    float l0 = w0 - __uint_as_float(b0 & 0xFFFF0000u);
    float l1 = w1 - __uint_as_float(b1 & 0xFFFF0000u);
    uint32_t lo;
    asm("cvt.rn.bf16x2.f32 %0, %1, %2;" : "=r"(lo) : "f"(l1), "f"(l0));

    int kstep = kp >> 3;
    int natom = h >> 3;
    int pair  = natom >> 1;
    int q     = natom & 1;
    int lane  = 4 * (h & 7) + (kp & 3);
    int reg   = (kp >> 2) & 1;
    int out   = ((kstep * 8 + pair) * 32 + lane) * 4 + q * 2 + reg;
    g_Bh[out] = hi;
    g_Bl[out] = lo;
}

// ---------------------------------------------------------------------------
__device__ __forceinline__ void mma_bf16(float* d, const uint32_t* a,
                                         uint32_t b0, uint32_t b1) {
    asm volatile(
        "mma.sync.aligned.m16n8k16.row.col.f32.bf16.bf16.f32 "
        "{%0,%1,%2,%3}, {%4,%5,%6,%7}, {%8,%9}, {%0,%1,%2,%3};"
        : "+f"(d[0]), "+f"(d[1]), "+f"(d[2]), "+f"(d[3])
        : "r"(a[0]), "r"(a[1]), "r"(a[2]), "r"(a[3]), "r"(b0), "r"(b1));
}
__device__ __forceinline__ uint32_t smem_u32(const void* p) {
    uint32_t a;
    asm("{ .reg .u64 t; cvta.to.shared.u64 t, %1; cvt.u32.u64 %0, t; }"
        : "=r"(a) : "l"(p));
    return a;
}
__device__ __forceinline__ void cp_async16(uint32_t s, const void* g) {
    asm volatile("cp.async.cg.shared.global [%0], [%1], 16;"
                 :: "r"(s), "l"(g) : "memory");
}
__device__ __forceinline__ float ex2f(float x) {
    float r;
    asm("ex2.approx.ftz.f32 %0, %1;" : "=f"(r) : "f"(x));
    return r;
}
// Reciprocal on the FMA pipe (no MUFU): bit-trick seed + 2 Newton steps
// (seed ~3.4e-2 rel err -> 1.2e-3 -> 1.4e-6; sufficient vs 1e-3 bound).
__device__ __forceinline__ float nrcp(float s) {
    float y = __uint_as_float(0x7EF311C3u - __float_as_uint(s));
    y = y * fmaf(-s, y, 2.0f);
    y = y * fmaf(-s, y, 2.0f);
    return y;
}

// ---------------------------------------------------------------------------
// Kernel 1: vm = X @ W^T via mma.sync bf16 3-term split (R11, unchanged —
// measured at the legacy-HMMA pipe floor).
// ---------------------------------------------------------------------------
__global__ __launch_bounds__(256, 2) void gemm_vm_tc(const float* __restrict__ X) {
    __shared__ uint32_t sA[4096];       // 16KB: hi[2048] | lo[2048]
    __shared__ uint32_t sB[2][4096];    // 32KB
    uint32_t* sAh = sA;
    uint32_t* sAl = sA + 2048;

    const int tid  = threadIdx.x;
    const int wid  = tid >> 5;
    const int lane = tid & 31;
    const int row0 = blockIdx.x * 128;
    const int wm   = wid & 3;
    const int wn   = wid >> 2;

    const int ar[4] = { (tid + 0)   >> 3, (tid + 256) >> 3,
                        (tid + 512) >> 3, (tid + 768) >> 3 };
    const int ac4   = tid & 7;

    float acc[2][8][4];
    #pragma unroll
    for (int i = 0; i < 2; ++i)
        #pragma unroll
        for (int j = 0; j < 8; ++j)
            #pragma unroll
            for (int q = 0; q < 4; ++q) acc[i][j][q] = 0.f;

    float4 pref[4];
    #pragma unroll
    for (int j = 0; j < 4; ++j)
        pref[j] = __ldg(reinterpret_cast<const float4*>(
                            X + (size_t)(row0 + ar[j]) * NE) + ac4);
    {
        const char* gh = reinterpret_cast<const char*>(g_Bh);
        const char* gl = reinterpret_cast<const char*>(g_Bl);
        uint32_t db = smem_u32(sB[0]);
        int e = tid * 16;
        cp_async16(db + e,               gh + e);
        cp_async16(db + 8192 + e,        gl + e);
        cp_async16(db + e + 4096,        gh + e + 4096);
        cp_async16(db + 8192 + e + 4096, gl + e + 4096);
        asm volatile("cp.async.commit_group;" ::: "memory");
    }

    for (int c = 0; c < NCH; ++c) {
        const int cur = c & 1;
        __syncthreads();   // prior MMA reads of sA / sB[cur^1] retired

        #pragma unroll
        for (int j = 0; j < 4; ++j) {
            float4 v = pref[j];
            uint32_t x0 = __float_as_uint(v.x), x1 = __float_as_uint(v.y);
            uint32_t x2 = __float_as_uint(v.z), x3 = __float_as_uint(v.w);
            uint32_t hi01, hi23;
            asm("prmt.b32 %0, %1, %2, 0x7632;" : "=r"(hi01) : "r"(x0), "r"(x1));
            asm("prmt.b32 %0, %1, %2, 0x7632;" : "=r"(hi23) : "r"(x2), "r"(x3));
            float l0 = v.x - __uint_as_float(x0 & 0xFFFF0000u);
            float l1 = v.y - __uint_as_float(x1 & 0xFFFF0000u);
            float l2 = v.z - __uint_as_float(x2 & 0xFFFF0000u);
            float l3 = v.w - __uint_as_float(x3 & 0xFFFF0000u);
            uint32_t lo01, lo23;
            asm("cvt.rn.bf16x2.f32 %0, %1, %2;" : "=r"(lo01) : "f"(l1), "f"(l0));
            asm("cvt.rn.bf16x2.f32 %0, %1, %2;" : "=r"(lo23) : "f"(l3), "f"(l2));
            int rr = ar[j] & 15, a = ar[j] >> 4;
            #pragma unroll
            for (int p = 0; p < 2; ++p) {
                int cc = 2 * ac4 + p;
                int s  = cc >> 3;
                int c8 = cc & 7;
                int ln = (rr & 7) * 4 + (c8 & 3);
                int rg = (rr >> 3) + 2 * (c8 >> 2);
                int e  = ((s * 8 + a) * 32 + ln) * 4 + rg;
                sAh[e] = p ? hi23 : hi01;
                sAl[e] = p ? lo23 : lo01;
            }
        }

        if (c + 1 < NCH) {
            const char* gh = reinterpret_cast<const char*>(g_Bh + (c + 1) * 2048);
            const char* gl = reinterpret_cast<const char*>(g_Bl + (c + 1) * 2048);
            uint32_t db = smem_u32(sB[cur ^ 1]);
            int e = tid * 16;
            cp_async16(db + e,               gh + e);
            cp_async16(db + 8192 + e,        gl + e);
            cp_async16(db + e + 4096,        gh + e + 4096);
            cp_async16(db + 8192 + e + 4096, gl + e + 4096);
            asm volatile("cp.async.commit_group;" ::: "memory");
            const float* Xn = X + (c + 1) * 32;
            #pragma unroll
            for (int j = 0; j < 4; ++j)
                pref[j] = __ldg(reinterpret_cast<const float4*>(
                                    Xn + (size_t)(row0 + ar[j]) * NE) + ac4);
            asm volatile("cp.async.wait_group 1;" ::: "memory");
        } else {
            asm volatile("cp.async.wait_group 0;" ::: "memory");
        }
        __syncthreads();   // sA converted + sB[cur] landed

        uint32_t* Bh = sB[cur];
        uint32_t* Bl = sB[cur] + 2048;

        #pragma unroll
        for (int s = 0; s < 2; ++s) {
            uint32_t ah[2][4], al[2][4];
            #pragma unroll
            for (int i = 0; i < 2; ++i) {
                const uint32_t* pa = &sAh[((s * 8 + wm * 2 + i) * 32 + lane) * 4];
                ah[i][0] = pa[0]; ah[i][1] = pa[1]; ah[i][2] = pa[2]; ah[i][3] = pa[3];
                const uint32_t* pl = &sAl[((s * 8 + wm * 2 + i) * 32 + lane) * 4];
                al[i][0] = pl[0]; al[i][1] = pl[1]; al[i][2] = pl[2]; al[i][3] = pl[3];
            }
            #pragma unroll
            for (int jh = 0; jh < 2; ++jh) {
                uint4 bhp[2], blp[2];
                #pragma unroll
                for (int jp = 0; jp < 2; ++jp) {
                    int pi = wn * 4 + jh * 2 + jp;
                    bhp[jp] = *reinterpret_cast<const uint4*>(
                        &Bh[((s * 8 + pi) * 32 + lane) * 4]);
                    blp[jp] = *reinterpret_cast<const uint4*>(
                        &Bl[((s * 8 + pi) * 32 + lane) * 4]);
                }
                const uint32_t bh[4][2] = {
                    {bhp[0].x, bhp[0].y}, {bhp[0].z, bhp[0].w},
                    {bhp[1].x, bhp[1].y}, {bhp[1].z, bhp[1].w}};
                const uint32_t bl[4][2] = {
                    {blp[0].x, blp[0].y}, {blp[0].z, blp[0].w},
                    {blp[1].x, blp[1].y}, {blp[1].z, blp[1].w}};
                #pragma unroll
                for (int i = 0; i < 2; ++i)
                    #pragma unroll
                    for (int jj = 0; jj < 4; ++jj) {
                        float* d = acc[i][jh * 4 + jj];
                        mma_bf16(d, ah[i], bh[jj][0], bh[jj][1]);
                        mma_bf16(d, ah[i], bl[jj][0], bl[jj][1]);
                        mma_bf16(d, al[i], bh[jj][0], bh[jj][1]);
                    }
            }
        }
    }

    #pragma unroll
    for (int i = 0; i < 2; ++i) {
        int grow = row0 + wm * 32 + i * 16 + (lane >> 2);
        #pragma unroll
        for (int j = 0; j < 8; ++j) {
            int gcol = wn * 64 + j * 8 + 2 * (lane & 3);
            float2* p0 = reinterpret_cast<float2*>(&g_vm[(size_t)grow * H + gcol]);
            float2* p1 = reinterpret_cast<float2*>(&g_vm[(size_t)(grow + 8) * H + gcol]);
            *p0 = make_float2(acc[i][j][0], acc[i][j][1]);
            *p1 = make_float2(acc[i][j][2], acc[i][j][3]);
        }
    }
}

// ---------------------------------------------------------------------------
// Kernel 2: fused softmax head, FOUR batches per CTA: one cov LDG.128 per
// (warp,h) feeds 4 batches (16 EX2, 4 trees, 4 FMA sets). Grid 4096 x 128.
// ---------------------------------------------------------------------------
__global__ __launch_bounds__(128) void head_out(const float* __restrict__ cov,
                                                const float* __restrict__ bias,
                                                float* __restrict__ out) {
    __shared__ float4 mv[H];           // (m0..m3)*log2e per h
    __shared__ float4 vv[H];           // (v0..v3) per h
    __shared__ float  part[4][4][H];   // [warp][batch][col] 8KB

    const int b0 = blockIdx.x * 4;
    const int t  = threadIdx.x;
    const int w  = t >> 5;
    const int l  = t & 31;
    const int hbase = w * 32;
    const float L2E = 1.4426950408889634f;

    mv[t] = make_float4(g_vm[(size_t)(2 * (b0 + 0) + 1) * H + t] * L2E,
                        g_vm[(size_t)(2 * (b0 + 1) + 1) * H + t] * L2E,
                        g_vm[(size_t)(2 * (b0 + 2) + 1) * H + t] * L2E,
                        g_vm[(size_t)(2 * (b0 + 3) + 1) * H + t] * L2E);
    vv[t] = make_float4(g_vm[(size_t)(2 * (b0 + 0) + 0) * H + t],
                        g_vm[(size_t)(2 * (b0 + 1) + 0) * H + t],
                        g_vm[(size_t)(2 * (b0 + 2) + 0) * H + t],
                        g_vm[(size_t)(2 * (b0 + 3) + 0) * H + t]);
    __syncthreads();

    float acc[4][4];
    #pragma unroll
    for (int j = 0; j < 4; ++j)
        #pragma unroll
        for (int q = 0; q < 4; ++q) acc[j][q] = 0.f;

    #pragma unroll 4
    for (int i = 0; i < 32; ++i) {
        const int h = hbase + i;
        const float4 m = mv[h];
        const float4 c = __ldg(reinterpret_cast<const float4*>(
                                   cov + (size_t)h * H) + l);
        float e[4][4];
        const float mj[4] = {m.x, m.y, m.z, m.w};
        #pragma unroll
        for (int j = 0; j < 4; ++j) {
            e[j][0] = ex2f(mj[j] * c.x);
            e[j][1] = ex2f(mj[j] * c.y);
            e[j][2] = ex2f(mj[j] * c.z);
            e[j][3] = ex2f(mj[j] * c.w);
        }
        float s[4];
        #pragma unroll
        for (int j = 0; j < 4; ++j)
            s[j] = (e[j][0] + e[j][1]) + (e[j][2] + e[j][3]);
        #pragma unroll
        for (int d = 16; d > 0; d >>= 1) {
            #pragma unroll
            for (int j = 0; j < 4; ++j)
                s[j] += __shfl_xor_sync(0xffffffffu, s[j], d);
        }
        const float4 v = vv[h];
        const float vj[4] = {v.x, v.y, v.z, v.w};
        #pragma unroll
        for (int j = 0; j < 4; ++j) {
            const float wj = vj[j] * nrcp(s[j]);
            acc[j][0] = fmaf(wj, e[j][0], acc[j][0]);
            acc[j][1] = fmaf(wj, e[j][1], acc[j][1]);
            acc[j][2] = fmaf(wj, e[j][2], acc[j][2]);
            acc[j][3] = fmaf(wj, e[j][3], acc[j][3]);
        }
    }

    #pragma unroll
    for (int j = 0; j < 4; ++j)
        *reinterpret_cast<float4*>(&part[w][j][4 * l]) =
            make_float4(acc[j][0], acc[j][1], acc[j][2], acc[j][3]);
    __syncthreads();

    const float bb = __ldg(bias + t);
    #pragma unroll
    for (int j = 0; j < 4; ++j)
        out[(size_t)(b0 + j) * H + t] =
            ((part[0][j][t] + part[1][j][t]) +
             (part[2][j][t] + part[3][j][t])) + bb;
}

// ---------------------------------------------------------------------------
extern "C" void kernel_launch(void* const* d_in, const int* in_sizes, int n_in,
                              void* d_out, int out_size) {
    const float* x    = (const float*)d_in[0];  // [16384,2,1024]
    const float* W    = (const float*)d_in[1];  // [128,1024]
    const float* cov  = (const float*)d_in[2];  // [128,128]
    const float* bias = (const float*)d_in[3];  // [128]
    float*       out  = (float*)d_out;          // [16384,128]

    prep_w<<<(H * NE / 2 + 255) / 256, 256>>>(W);
    gemm_vm_tc<<<R_TOTAL / 128, 256>>>(x);
    head_out<<<4096, 128>>>(cov, bias, out);
}

// round 14
// speedup vs baseline: 1.7219x; 1.0544x over previous
#include <cuda_runtime.h>
#include <cuda_bf16.h>
#include <cstdint>

#define R_TOTAL 32768   // 16384 b * 2 (values,mask)
#define NE      1024
#define H       128
#define NCH     32      // K-chunks of 32

// Scratch: vm[2b+0]=values row, vm[2b+1]=mask row.
__device__ float g_vm[(size_t)R_TOTAL * H];

// W pre-split into bf16 hi/lo, packed in PAIRED m16n8k16 B-fragment order:
//   [kstep(64)][pair(8)][lane(32)][q(2)*2+reg]  (natom = 2*pair + q)
__device__ uint32_t g_Bh[64 * 8 * 32 * 4];
__device__ uint32_t g_Bl[64 * 8 * 32 * 4];

// ---------------------------------------------------------------------------
// Kernel 0: split W -> bf16 hi/lo in paired B-fragment layout.
// ---------------------------------------------------------------------------
__global__ void prep_w(const float* __restrict__ W) {
    int idx = blockIdx.x * 256 + threadIdx.x;
    if (idx >= H * (NE / 2)) return;
    int h  = idx >> 9;
    int kp = idx & 511;
    int k  = kp * 2;

    float w0 = W[(size_t)h * NE + k];
    float w1 = W[(size_t)h * NE + k + 1];
    uint32_t b0 = __float_as_uint(w0), b1 = __float_as_uint(w1);
    uint32_t hi;
    asm("prmt.b32 %0, %1, %2, 0x7632;" : "=r"(hi) : "r"(b0), "r"(b1));
    float l0 = w0 - __uint_as_float(b0 & 0xFFFF0000u);
    float l1 = w1 - __uint_as_float(b1 & 0xFFFF0000u);
    uint32_t lo;
    asm("cvt.rn.bf16x2.f32 %0, %1, %2;" : "=r"(lo) : "f"(l1), "f"(l0));

    int kstep = kp >> 3;
    int natom = h >> 3;
    int pair  = natom >> 1;
    int q     = natom & 1;
    int lane  = 4 * (h & 7) + (kp & 3);
    int reg   = (kp >> 2) & 1;
    int out   = ((kstep * 8 + pair) * 32 + lane) * 4 + q * 2 + reg;
    g_Bh[out] = hi;
    g_Bl[out] = lo;
}

// ---------------------------------------------------------------------------
__device__ __forceinline__ void mma_bf16(float* d, const uint32_t* a,
                                         uint32_t b0, uint32_t b1) {
    asm volatile(
        "mma.sync.aligned.m16n8k16.row.col.f32.bf16.bf16.f32 "
        "{%0,%1,%2,%3}, {%4,%5,%6,%7}, {%8,%9}, {%0,%1,%2,%3};"
        : "+f"(d[0]), "+f"(d[1]), "+f"(d[2]), "+f"(d[3])
        : "r"(a[0]), "r"(a[1]), "r"(a[2]), "r"(a[3]), "r"(b0), "r"(b1));
}
__device__ __forceinline__ uint32_t smem_u32(const void* p) {
    uint32_t a;
    asm("{ .reg .u64 t; cvta.to.shared.u64 t, %1; cvt.u32.u64 %0, t; }"
        : "=r"(a) : "l"(p));
    return a;
}
__device__ __forceinline__ void cp_async16(uint32_t s, const void* g) {
    asm volatile("cp.async.cg.shared.global [%0], [%1], 16;"
                 :: "r"(s), "l"(g) : "memory");
}
__device__ __forceinline__ float ex2f(float x) {
    float r;
    asm("ex2.approx.ftz.f32 %0, %1;" : "=f"(r) : "f"(x));
    return r;
}
// Reciprocal on the FMA pipe (no MUFU): bit-trick seed + 2 Newton steps.
__device__ __forceinline__ float nrcp(float s) {
    float y = __uint_as_float(0x7EF311C3u - __float_as_uint(s));
    y = y * fmaf(-s, y, 2.0f);
    y = y * fmaf(-s, y, 2.0f);
    return y;
}

// ---------------------------------------------------------------------------
// Kernel 1: vm = X @ W^T via mma.sync bf16 3-term split (unchanged — at the
// legacy-HMMA pipe floor).
// ---------------------------------------------------------------------------
__global__ __launch_bounds__(256, 2) void gemm_vm_tc(const float* __restrict__ X) {
    __shared__ uint32_t sA[4096];       // 16KB: hi[2048] | lo[2048]
    __shared__ uint32_t sB[2][4096];    // 32KB
    uint32_t* sAh = sA;
    uint32_t* sAl = sA + 2048;

    const int tid  = threadIdx.x;
    const int wid  = tid >> 5;
    const int lane = tid & 31;
    const int row0 = blockIdx.x * 128;
    const int wm   = wid & 3;
    const int wn   = wid >> 2;

    const int ar[4] = { (tid + 0)   >> 3, (tid + 256) >> 3,
                        (tid + 512) >> 3, (tid + 768) >> 3 };
    const int ac4   = tid & 7;

    float acc[2][8][4];
    #pragma unroll
    for (int i = 0; i < 2; ++i)
        #pragma unroll
        for (int j = 0; j < 8; ++j)
            #pragma unroll
            for (int q = 0; q < 4; ++q) acc[i][j][q] = 0.f;

    float4 pref[4];
    #pragma unroll
    for (int j = 0; j < 4; ++j)
        pref[j] = __ldg(reinterpret_cast<const float4*>(
                            X + (size_t)(row0 + ar[j]) * NE) + ac4);
    {
        const char* gh = reinterpret_cast<const char*>(g_Bh);
        const char* gl = reinterpret_cast<const char*>(g_Bl);
        uint32_t db = smem_u32(sB[0]);
        int e = tid * 16;
        cp_async16(db + e,               gh + e);
        cp_async16(db + 8192 + e,        gl + e);
        cp_async16(db + e + 4096,        gh + e + 4096);
        cp_async16(db + 8192 + e + 4096, gl + e + 4096);
        asm volatile("cp.async.commit_group;" ::: "memory");
    }

    for (int c = 0; c < NCH; ++c) {
        const int cur = c & 1;
        __syncthreads();   // prior MMA reads of sA / sB[cur^1] retired

        #pragma unroll
        for (int j = 0; j < 4; ++j) {
            float4 v = pref[j];
            uint32_t x0 = __float_as_uint(v.x), x1 = __float_as_uint(v.y);
            uint32_t x2 = __float_as_uint(v.z), x3 = __float_as_uint(v.w);
            uint32_t hi01, hi23;
            asm("prmt.b32 %0, %1, %2, 0x7632;" : "=r"(hi01) : "r"(x0), "r"(x1));
            asm("prmt.b32 %0, %1, %2, 0x7632;" : "=r"(hi23) : "r"(x2), "r"(x3));
            float l0 = v.x - __uint_as_float(x0 & 0xFFFF0000u);
            float l1 = v.y - __uint_as_float(x1 & 0xFFFF0000u);
            float l2 = v.z - __uint_as_float(x2 & 0xFFFF0000u);
            float l3 = v.w - __uint_as_float(x3 & 0xFFFF0000u);
            uint32_t lo01, lo23;
            asm("cvt.rn.bf16x2.f32 %0, %1, %2;" : "=r"(lo01) : "f"(l1), "f"(l0));
            asm("cvt.rn.bf16x2.f32 %0, %1, %2;" : "=r"(lo23) : "f"(l3), "f"(l2));
            int rr = ar[j] & 15, a = ar[j] >> 4;
            #pragma unroll
            for (int p = 0; p < 2; ++p) {
                int cc = 2 * ac4 + p;
                int s  = cc >> 3;
                int c8 = cc & 7;
                int ln = (rr & 7) * 4 + (c8 & 3);
                int rg = (rr >> 3) + 2 * (c8 >> 2);
                int e  = ((s * 8 + a) * 32 + ln) * 4 + rg;
                sAh[e] = p ? hi23 : hi01;
                sAl[e] = p ? lo23 : lo01;
            }
        }

        if (c + 1 < NCH) {
            const char* gh = reinterpret_cast<const char*>(g_Bh + (c + 1) * 2048);
            const char* gl = reinterpret_cast<const char*>(g_Bl + (c + 1) * 2048);
            uint32_t db = smem_u32(sB[cur ^ 1]);
            int e = tid * 16;
            cp_async16(db + e,               gh + e);
            cp_async16(db + 8192 + e,        gl + e);
            cp_async16(db + e + 4096,        gh + e + 4096);
            cp_async16(db + 8192 + e + 4096, gl + e + 4096);
            asm volatile("cp.async.commit_group;" ::: "memory");
            const float* Xn = X + (c + 1) * 32;
            #pragma unroll
            for (int j = 0; j < 4; ++j)
                pref[j] = __ldg(reinterpret_cast<const float4*>(
                                    Xn + (size_t)(row0 + ar[j]) * NE) + ac4);
            asm volatile("cp.async.wait_group 1;" ::: "memory");
        } else {
            asm volatile("cp.async.wait_group 0;" ::: "memory");
        }
        __syncthreads();   // sA converted + sB[cur] landed

        uint32_t* Bh = sB[cur];
        uint32_t* Bl = sB[cur] + 2048;

        #pragma unroll
        for (int s = 0; s < 2; ++s) {
            uint32_t ah[2][4], al[2][4];
            #pragma unroll
            for (int i = 0; i < 2; ++i) {
                const uint32_t* pa = &sAh[((s * 8 + wm * 2 + i) * 32 + lane) * 4];
                ah[i][0] = pa[0]; ah[i][1] = pa[1]; ah[i][2] = pa[2]; ah[i][3] = pa[3];
                const uint32_t* pl = &sAl[((s * 8 + wm * 2 + i) * 32 + lane) * 4];
                al[i][0] = pl[0]; al[i][1] = pl[1]; al[i][2] = pl[2]; al[i][3] = pl[3];
            }
            #pragma unroll
            for (int jh = 0; jh < 2; ++jh) {
                uint4 bhp[2], blp[2];
                #pragma unroll
                for (int jp = 0; jp < 2; ++jp) {
                    int pi = wn * 4 + jh * 2 + jp;
                    bhp[jp] = *reinterpret_cast<const uint4*>(
                        &Bh[((s * 8 + pi) * 32 + lane) * 4]);
                    blp[jp] = *reinterpret_cast<const uint4*>(
                        &Bl[((s * 8 + pi) * 32 + lane) * 4]);
                }
                const uint32_t bh[4][2] = {
                    {bhp[0].x, bhp[0].y}, {bhp[0].z, bhp[0].w},
                    {bhp[1].x, bhp[1].y}, {bhp[1].z, bhp[1].w}};
                const uint32_t bl[4][2] = {
                    {blp[0].x, blp[0].y}, {blp[0].z, blp[0].w},
                    {blp[1].x, blp[1].y}, {blp[1].z, blp[1].w}};
                #pragma unroll
                for (int i = 0; i < 2; ++i)
                    #pragma unroll
                    for (int jj = 0; jj < 4; ++jj) {
                        float* d = acc[i][jh * 4 + jj];
                        mma_bf16(d, ah[i], bh[jj][0], bh[jj][1]);
                        mma_bf16(d, ah[i], bl[jj][0], bl[jj][1]);
                        mma_bf16(d, al[i], bh[jj][0], bh[jj][1]);
                    }
            }
        }
    }

    #pragma unroll
    for (int i = 0; i < 2; ++i) {
        int grow = row0 + wm * 32 + i * 16 + (lane >> 2);
        #pragma unroll
        for (int j = 0; j < 8; ++j) {
            int gcol = wn * 64 + j * 8 + 2 * (lane & 3);
            float2* p0 = reinterpret_cast<float2*>(&g_vm[(size_t)grow * H + gcol]);
            float2* p1 = reinterpret_cast<float2*>(&g_vm[(size_t)(grow + 8) * H + gcol]);
            *p0 = make_float2(acc[i][j][0], acc[i][j][1]);
            *p1 = make_float2(acc[i][j][2], acc[i][j][3]);
        }
    }
}

// ---------------------------------------------------------------------------
// Kernel 2: fused softmax head v3 — 8-lane Z-reduction.
// 4 batches/CTA, 128 thr. Lane l: hgrp=l>>3, kc=l&7 (16 k each).
// Warp processes 4 h at once -> xor tree d=4,2,1 = 3 SHFL per (4h,batch)
// (was 5 per (1h,batch)): SHFL/batch 640 -> 96. Combine via padded smem.
// ---------------------------------------------------------------------------
__global__ __launch_bounds__(128) void head_out(const float* __restrict__ cov,
                                                const float* __restrict__ bias,
                                                float* __restrict__ out) {
    __shared__ float4 mv[H];               // per h: m*log2e for 4 batches
    __shared__ float4 vv[H];               // per h: v for 4 batches
    __shared__ float  part[16][4][8][20];  // [slice][batch][kc][q pad20] 40KB

    const int b0 = blockIdx.x * 4;
    const int t  = threadIdx.x;
    const int w  = t >> 5;
    const int l  = t & 31;
    const int hgrp = l >> 3;
    const int kc   = l & 7;
    const int hbase = w * 32;
    const float L2E = 1.4426950408889634f;

    mv[t] = make_float4(g_vm[(size_t)(2 * (b0 + 0) + 1) * H + t] * L2E,
                        g_vm[(size_t)(2 * (b0 + 1) + 1) * H + t] * L2E,
                        g_vm[(size_t)(2 * (b0 + 2) + 1) * H + t] * L2E,
                        g_vm[(size_t)(2 * (b0 + 3) + 1) * H + t] * L2E);
    vv[t] = make_float4(g_vm[(size_t)(2 * (b0 + 0) + 0) * H + t],
                        g_vm[(size_t)(2 * (b0 + 1) + 0) * H + t],
                        g_vm[(size_t)(2 * (b0 + 2) + 0) * H + t],
                        g_vm[(size_t)(2 * (b0 + 3) + 0) * H + t]);
    __syncthreads();

    float acc[4][16];
    #pragma unroll
    for (int j = 0; j < 4; ++j)
        #pragma unroll
        for (int q = 0; q < 16; ++q) acc[j][q] = 0.f;

    #pragma unroll 2
    for (int pass = 0; pass < 8; ++pass) {
        const int h = hbase + pass * 4 + hgrp;
        const float4* cp = reinterpret_cast<const float4*>(
                               cov + (size_t)h * H + kc * 16);
        const float4 c0 = __ldg(cp + 0);
        const float4 c1 = __ldg(cp + 1);
        const float4 c2 = __ldg(cp + 2);
        const float4 c3 = __ldg(cp + 3);
        const float4 m4 = mv[h];
        const float4 v4 = vv[h];
        const float mj4[4] = {m4.x, m4.y, m4.z, m4.w};
        const float vj4[4] = {v4.x, v4.y, v4.z, v4.w};

        #pragma unroll
        for (int j = 0; j < 4; ++j) {
            const float mj = mj4[j];
            float e[16];
            e[0]  = ex2f(mj * c0.x); e[1]  = ex2f(mj * c0.y);
            e[2]  = ex2f(mj * c0.z); e[3]  = ex2f(mj * c0.w);
            e[4]  = ex2f(mj * c1.x); e[5]  = ex2f(mj * c1.y);
            e[6]  = ex2f(mj * c1.z); e[7]  = ex2f(mj * c1.w);
            e[8]  = ex2f(mj * c2.x); e[9]  = ex2f(mj * c2.y);
            e[10] = ex2f(mj * c2.z); e[11] = ex2f(mj * c2.w);
            e[12] = ex2f(mj * c3.x); e[13] = ex2f(mj * c3.y);
            e[14] = ex2f(mj * c3.z); e[15] = ex2f(mj * c3.w);

            float s = (((e[0] + e[1]) + (e[2] + e[3])) +
                       ((e[4] + e[5]) + (e[6] + e[7]))) +
                      (((e[8] + e[9]) + (e[10] + e[11])) +
                       ((e[12] + e[13]) + (e[14] + e[15])));
            s += __shfl_xor_sync(0xffffffffu, s, 4);
            s += __shfl_xor_sync(0xffffffffu, s, 2);
            s += __shfl_xor_sync(0xffffffffu, s, 1);

            const float wj = vj4[j] * nrcp(s);
            #pragma unroll
            for (int q = 0; q < 16; ++q)
                acc[j][q] = fmaf(wj, e[q], acc[j][q]);
        }
    }

    // store partials: slice = w*4 + hgrp; pad-20 rows keep STS.128 aligned
    // and kc-banks distinct (kc*20 mod 32 all distinct).
    const int slice = w * 4 + hgrp;
    #pragma unroll
    for (int j = 0; j < 4; ++j)
        #pragma unroll
        for (int qi = 0; qi < 4; ++qi)
            *reinterpret_cast<float4*>(&part[slice][j][kc][qi * 4]) =
                make_float4(acc[j][qi * 4 + 0], acc[j][qi * 4 + 1],
                            acc[j][qi * 4 + 2], acc[j][qi * 4 + 3]);
    __syncthreads();

    // combine: thread t owns column k = t
    const int kc2 = t >> 4;
    const int q2  = t & 15;
    const float bb = __ldg(bias + t);
    #pragma unroll
    for (int j = 0; j < 4; ++j) {
        float s = 0.f;
        #pragma unroll
        for (int sl = 0; sl < 16; ++sl)
            s += part[sl][j][kc2][q2];
        out[(size_t)(b0 + j) * H + t] = s + bb;
    }
}

// ---------------------------------------------------------------------------
extern "C" void kernel_launch(void* const* d_in, const int* in_sizes, int n_in,
                              void* d_out, int out_size) {
    const float* x    = (const float*)d_in[0];  // [16384,2,1024]
    const float* W    = (const float*)d_in[1];  // [128,1024]
    const float* cov  = (const float*)d_in[2];  // [128,128]
    const float* bias = (const float*)d_in[3];  // [128]
    float*       out  = (float*)d_out;          // [16384,128]

    prep_w<<<(H * NE / 2 + 255) / 256, 256>>>(W);
    gemm_vm_tc<<<R_TOTAL / 128, 256>>>(x);
    head_out<<<4096, 128>>>(cov, bias, out);
}